// round 13
// baseline (speedup 1.0000x reference)
#include <cuda_runtime.h>
#include <cuda_fp16.h>
#include <cstdint>

// ---------------------------------------------------------------------------
// GAT (4 layers) + FC on GB300.  INSTRUMENTED ROUND:
//   - gemm0 hoisted to launch slot 4 (ncu capture slot) for profiling.
//   - layer-3 agg runs twice (2nd into dead scratch) to measure its cost.
//   - agg edge loop software-pipelined (col int4 prefetch).
// Pipeline unchanged otherwise: CSR-by-dst once, self-loop-score softmax,
// inline edge weights, fp16 gathers, aggregate on cheap side of GEMM.
// ---------------------------------------------------------------------------

#define MAXN 50176
#define MAXEL 1703936
#define SCANB 256

__device__ float  g_h0[(size_t)MAXN * 128];
__device__ float  g_h1[(size_t)MAXN * 128];
__device__ __half g_ha[(size_t)MAXN * 128];
__device__ __half g_hb[(size_t)MAXN * 128];
__device__ float  g_as[MAXN];
__device__ float2 g_pair[MAXN];
__device__ float  g_us[128];
__device__ float  g_ud[128];
__device__ int    g_rp[MAXN + 1];
__device__ int    g_cnt[MAXN];
__device__ int    g_cur[MAXN];
__device__ int    g_col[MAXEL];
__device__ int    g_psum[MAXN / SCANB + 1];
__device__ int    g_is64;

__device__ __forceinline__ float lrelu(float e) { return e > 0.f ? e : 0.2f * e; }

// ---------------------------------------------------------------------------
__global__ void detect_k(const int* __restrict__ w) {
    int lane = threadIdx.x;
    int bad = (w[lane * 2 + 1] != 0);
    unsigned any = __ballot_sync(0xffffffffu, bad);
    if (lane == 0) g_is64 = (any == 0u);
}

__device__ __forceinline__ int load_idx(const void* ei, size_t pos) {
    if (g_is64) return (int)((const long long*)ei)[pos];
    return ((const int*)ei)[pos];
}

// ---------------------------------------------------------------------------
__global__ void zero_cnt_k(int* cnt, int n) {
    int i = blockIdx.x * blockDim.x + threadIdx.x;
    if (i < n) cnt[i] = 0;
}

__global__ void count_k(const void* __restrict__ ei, int E, int N, int* cnt) {
    int i = blockIdx.x * blockDim.x + threadIdx.x;
    int M = E + N;
    if (i >= M) return;
    int d = (i < E) ? load_idx(ei, (size_t)E + i) : (i - E);
    if (d < 0 || d >= N) d = 0;
    atomicAdd(&cnt[d], 1);
}

__global__ void scan1_k(const int* __restrict__ cnt, int* psum, int n) {
    __shared__ int ss[8];
    int i = blockIdx.x * SCANB + threadIdx.x;
    int v = (i < n) ? cnt[i] : 0;
#pragma unroll
    for (int off = 16; off; off >>= 1) v += __shfl_xor_sync(0xffffffffu, v, off);
    if ((threadIdx.x & 31) == 0) ss[threadIdx.x >> 5] = v;
    __syncthreads();
    if (threadIdx.x == 0) {
        int t = 0;
#pragma unroll
        for (int k = 0; k < 8; k++) t += ss[k];
        psum[blockIdx.x] = t;
    }
}

__global__ void scan2_k(int* psum, int nb, int* rp, int n) {
    __shared__ int ss[SCANB];
    int tid = threadIdx.x;
    int v = (tid < nb) ? psum[tid] : 0;
    ss[tid] = v;
    __syncthreads();
#pragma unroll
    for (int off = 1; off < SCANB; off <<= 1) {
        int t = (tid >= off) ? ss[tid - off] : 0;
        __syncthreads();
        ss[tid] += t;
        __syncthreads();
    }
    if (tid < nb) psum[tid] = ss[tid] - v;
    if (tid == SCANB - 1) rp[n] = ss[SCANB - 1];
}

__global__ void scan3_k(const int* __restrict__ cnt, const int* __restrict__ psum,
                        int* rp, int* cur, int n) {
    __shared__ int ss[SCANB];
    int tid = threadIdx.x;
    int i = blockIdx.x * SCANB + tid;
    int v = (i < n) ? cnt[i] : 0;
    ss[tid] = v;
    __syncthreads();
#pragma unroll
    for (int off = 1; off < SCANB; off <<= 1) {
        int t = (tid >= off) ? ss[tid - off] : 0;
        __syncthreads();
        ss[tid] += t;
        __syncthreads();
    }
    if (i < n) {
        int r = ss[tid] - v + psum[blockIdx.x];
        rp[i] = r;
        cur[i] = r;
    }
}

__global__ void scatter_k(const void* __restrict__ ei, int E, int N,
                          int* cur, int* __restrict__ col) {
    int i = blockIdx.x * blockDim.x + threadIdx.x;
    int M = E + N;
    if (i >= M) return;
    int d, s;
    if (i < E) {
        d = load_idx(ei, (size_t)E + i);
        s = load_idx(ei, (size_t)i);
    } else {
        d = i - E;
        s = d;
    }
    if (d < 0 || d >= N) d = 0;
    if (s < 0 || s >= N) s = 0;
    int p = atomicAdd(&cur[d], 1);
    if (p >= 0 && p < MAXEL) col[p] = s;
}

// ---------------------------------------------------------------------------
template <int FIN, int FOUT>
__global__ void wa_k(const float* __restrict__ W, const float* __restrict__ a_s,
                     const float* __restrict__ a_d,
                     float* __restrict__ us, float* __restrict__ ud) {
    int i = threadIdx.x;
    if (i >= FIN) return;
    float s1 = 0.f, s2 = 0.f;
#pragma unroll 4
    for (int j = 0; j < FOUT; j++) {
        float w = W[i * FOUT + j];
        s1 = fmaf(w, a_s[j], s1);
        s2 = fmaf(w, a_d[j], s2);
    }
    us[i] = s1;
    ud[i] = s2;
}

// ---------------------------------------------------------------------------
template <int F>
__global__ void __launch_bounds__(256) score_k(
    const float* __restrict__ x, const float* __restrict__ us,
    const float* __restrict__ ud, float* __restrict__ as_out,
    float2* __restrict__ pair_out, int N)
{
    int node = blockIdx.x * 8 + (threadIdx.x >> 5);
    if (node >= N) return;
    int lane = threadIdx.x & 31;
    const float* xp = x + (size_t)node * F;
    float s1 = 0.f, s2 = 0.f;
#pragma unroll
    for (int i = lane; i < F; i += 32) {
        float xv = xp[i];
        s1 = fmaf(xv, us[i], s1);
        s2 = fmaf(xv, ud[i], s2);
    }
#pragma unroll
    for (int off = 16; off; off >>= 1) {
        s1 += __shfl_xor_sync(0xffffffffu, s1, off);
        s2 += __shfl_xor_sync(0xffffffffu, s2, off);
    }
    if (lane == 0) {
        as_out[node] = s1;
        pair_out[node] = make_float2(s2, lrelu(s1 + s2));
    }
}

// ---------------------------------------------------------------------------
template <int F>
__device__ __forceinline__ void gfma(const __half* __restrict__ hh, int src,
                                     int lane, float wt, float* acc) {
    constexpr int VEC = F / 32;
    const __half* p = hh + (size_t)src * F + lane * VEC;
    if constexpr (VEC == 4) {
        uint2 t = *(const uint2*)p;
        __half2 a = *reinterpret_cast<__half2*>(&t.x);
        __half2 b = *reinterpret_cast<__half2*>(&t.y);
        float2 fa = __half22float2(a), fb = __half22float2(b);
        acc[0] = fmaf(wt, fa.x, acc[0]); acc[1] = fmaf(wt, fa.y, acc[1]);
        acc[2] = fmaf(wt, fb.x, acc[2]); acc[3] = fmaf(wt, fb.y, acc[3]);
    } else if constexpr (VEC == 2) {
        float2 f = __half22float2(*(const __half2*)p);
        acc[0] = fmaf(wt, f.x, acc[0]); acc[1] = fmaf(wt, f.y, acc[1]);
    } else {
        acc[0] = fmaf(wt, __half2float(*p), acc[0]);
    }
}

// ---------------------------------------------------------------------------
// Aggregation: warp per dst node; inline weights; col prefetch pipeline.
// ---------------------------------------------------------------------------
template <int F, bool FINISH>
__global__ void __launch_bounds__(256) agg_k(
    const int* __restrict__ rp, const int* __restrict__ col,
    const float* __restrict__ as, const float2* __restrict__ pair,
    const __half* __restrict__ hh, const float* __restrict__ bias,
    float* __restrict__ out32, __half* __restrict__ out16, int N)
{
    constexpr int VEC = F / 32;
    int node = blockIdx.x * 8 + (threadIdx.x >> 5);
    if (node >= N) return;
    int lane = threadIdx.x & 31;
    int beg = rp[node], end = rp[node + 1];
    float2 pm = pair[node];
    float add = pm.x, m = pm.y;

    float acc[VEC];
#pragma unroll
    for (int v = 0; v < VEC; v++) acc[v] = 0.f;
    float s = 0.f;

    int j = beg;
    int jal = min(end, (beg + 3) & ~3);
    for (; j < jal; ++j) {
        int src = col[j];
        float wt = __expf(lrelu(as[src] + add) - m);
        s += wt;
        gfma<F>(hh, src, lane, wt, acc);
    }

    // software-pipelined main loop: next int4 col load in flight during body
    bool have = (j + 4 <= end);
    int4 c_next;
    if (have) c_next = *(const int4*)(col + j);
    while (have) {
        int4 c4 = c_next;
        j += 4;
        have = (j + 4 <= end);
        if (have) c_next = *(const int4*)(col + j);
        float a0 = as[c4.x], a1 = as[c4.y], a2 = as[c4.z], a3 = as[c4.w];
        float w0 = __expf(lrelu(a0 + add) - m);
        float w1 = __expf(lrelu(a1 + add) - m);
        float w2 = __expf(lrelu(a2 + add) - m);
        float w3 = __expf(lrelu(a3 + add) - m);
        s += (w0 + w1) + (w2 + w3);
        gfma<F>(hh, c4.x, lane, w0, acc);
        gfma<F>(hh, c4.y, lane, w1, acc);
        gfma<F>(hh, c4.z, lane, w2, acc);
        gfma<F>(hh, c4.w, lane, w3, acc);
    }
    for (; j < end; ++j) {
        int src = col[j];
        float wt = __expf(lrelu(as[src] + add) - m);
        s += wt;
        gfma<F>(hh, src, lane, wt, acc);
    }

    float inv = 1.f / s;
    float o[VEC];
#pragma unroll
    for (int v = 0; v < VEC; v++) {
        if constexpr (FINISH)
            o[v] = fmaxf(acc[v] * inv + bias[lane * VEC + v], 0.f);
        else
            o[v] = acc[v] * inv;
    }
    float* op = out32 + (size_t)node * F + lane * VEC;
    if constexpr (VEC == 4)      *(float4*)op = make_float4(o[0], o[1], o[2], o[3]);
    else if constexpr (VEC == 2) *(float2*)op = make_float2(o[0], o[1]);
    else                         *op = o[0];

    if (out16) {
        __half* hp = out16 + (size_t)node * F + lane * VEC;
        if constexpr (VEC == 4) {
            uint2 t;
            *reinterpret_cast<__half2*>(&t.x) = __floats2half2_rn(o[0], o[1]);
            *reinterpret_cast<__half2*>(&t.y) = __floats2half2_rn(o[2], o[3]);
            *(uint2*)hp = t;
        } else if constexpr (VEC == 2) {
            *(__half2*)hp = __floats2half2_rn(o[0], o[1]);
        } else {
            *hp = __float2half_rn(o[0]);
        }
    }
}

// ---------------------------------------------------------------------------
template <int FIN, int FOUT, int KC>
__global__ void __launch_bounds__(256) gat_gemm_k(
    const float* __restrict__ x, const float* __restrict__ W,
    const float* __restrict__ avs, const float* __restrict__ avd,
    __half* __restrict__ h16, float* __restrict__ as_out,
    float2* __restrict__ pair_out, int N)
{
    constexpr int VEC = FOUT / 32;
    constexpr int XR  = FIN / 32;
    constexpr int NCH = FIN / KC;
    __shared__ float sW[KC * FOUT];

    const int warp = threadIdx.x >> 5;
    const int lane = threadIdx.x & 31;
    const int row0 = (blockIdx.x * 8 + warp) * 4;

    float xr[4][XR];
#pragma unroll
    for (int r = 0; r < 4; r++) {
        const float* xp = x + (size_t)(row0 + r) * FIN;
#pragma unroll
        for (int i = 0; i < XR; i++)
            xr[r][i] = (row0 + r < N) ? xp[lane + 32 * i] : 0.f;
    }

    float acc[4][VEC];
#pragma unroll
    for (int r = 0; r < 4; r++)
#pragma unroll
        for (int v = 0; v < VEC; v++) acc[r][v] = 0.f;

#pragma unroll
    for (int c = 0; c < NCH; c++) {
        __syncthreads();
        for (int i = threadIdx.x; i < KC * FOUT; i += 256)
            sW[i] = W[c * KC * FOUT + i];
        __syncthreads();
#pragma unroll
        for (int kk = 0; kk < KC; kk++) {
            const int k = c * KC + kk;
            float wv[VEC];
            const float* wp = sW + kk * FOUT + lane * VEC;
            if constexpr (VEC == 4) {
                float4 t = *(const float4*)wp;
                wv[0] = t.x; wv[1] = t.y; wv[2] = t.z; wv[3] = t.w;
            } else if constexpr (VEC == 2) {
                float2 t = *(const float2*)wp;
                wv[0] = t.x; wv[1] = t.y;
            } else {
                wv[0] = *wp;
            }
#pragma unroll
            for (int r = 0; r < 4; r++) {
                float xk = __shfl_sync(0xffffffffu, xr[r][k >> 5], k & 31);
#pragma unroll
                for (int v = 0; v < VEC; v++)
                    acc[r][v] = fmaf(xk, wv[v], acc[r][v]);
            }
        }
    }

    float av1[VEC], av2[VEC];
#pragma unroll
    for (int v = 0; v < VEC; v++) {
        av1[v] = avs[lane * VEC + v];
        av2[v] = avd[lane * VEC + v];
    }
#pragma unroll
    for (int r = 0; r < 4; r++) {
        int row = row0 + r;
        float s1 = 0.f, s2 = 0.f;
#pragma unroll
        for (int v = 0; v < VEC; v++) {
            s1 = fmaf(acc[r][v], av1[v], s1);
            s2 = fmaf(acc[r][v], av2[v], s2);
        }
#pragma unroll
        for (int off = 16; off; off >>= 1) {
            s1 += __shfl_xor_sync(0xffffffffu, s1, off);
            s2 += __shfl_xor_sync(0xffffffffu, s2, off);
        }
        if (row < N) {
            __half* hp = h16 + (size_t)row * FOUT + lane * VEC;
            if constexpr (VEC == 4) {
                uint2 t;
                *reinterpret_cast<__half2*>(&t.x) = __floats2half2_rn(acc[r][0], acc[r][1]);
                *reinterpret_cast<__half2*>(&t.y) = __floats2half2_rn(acc[r][2], acc[r][3]);
                *(uint2*)hp = t;
            } else if constexpr (VEC == 2) {
                *(__half2*)hp = __floats2half2_rn(acc[r][0], acc[r][1]);
            } else {
                *hp = __float2half_rn(acc[r][0]);
            }
            if (lane == 0) {
                as_out[row] = s1;
                pair_out[row] = make_float2(s2, lrelu(s1 + s2));
            }
        }
    }
}

// ---------------------------------------------------------------------------
template <int FIN, int FOUT, int KC>
__global__ void __launch_bounds__(256) post_gemm_k(
    const float* __restrict__ x, const float* __restrict__ W,
    const float* __restrict__ b, float* __restrict__ out32,
    __half* __restrict__ out16, int N)
{
    constexpr int VEC = FOUT / 32;
    constexpr int XR  = FIN / 32;
    constexpr int NCH = FIN / KC;
    __shared__ float sW[KC * FOUT];

    const int warp = threadIdx.x >> 5;
    const int lane = threadIdx.x & 31;
    const int row0 = (blockIdx.x * 8 + warp) * 4;

    float xr[4][XR];
#pragma unroll
    for (int r = 0; r < 4; r++) {
        const float* xp = x + (size_t)(row0 + r) * FIN;
#pragma unroll
        for (int i = 0; i < XR; i++)
            xr[r][i] = (row0 + r < N) ? xp[lane + 32 * i] : 0.f;
    }

    float acc[4][VEC];
#pragma unroll
    for (int r = 0; r < 4; r++)
#pragma unroll
        for (int v = 0; v < VEC; v++) acc[r][v] = 0.f;

#pragma unroll
    for (int c = 0; c < NCH; c++) {
        __syncthreads();
        for (int i = threadIdx.x; i < KC * FOUT; i += 256)
            sW[i] = W[c * KC * FOUT + i];
        __syncthreads();
#pragma unroll
        for (int kk = 0; kk < KC; kk++) {
            const int k = c * KC + kk;
            float wv[VEC];
            const float* wp = sW + kk * FOUT + lane * VEC;
            if constexpr (VEC == 4) {
                float4 t = *(const float4*)wp;
                wv[0] = t.x; wv[1] = t.y; wv[2] = t.z; wv[3] = t.w;
            } else if constexpr (VEC == 2) {
                float2 t = *(const float2*)wp;
                wv[0] = t.x; wv[1] = t.y;
            } else {
                wv[0] = *wp;
            }
#pragma unroll
            for (int r = 0; r < 4; r++) {
                float xk = __shfl_sync(0xffffffffu, xr[r][k >> 5], k & 31);
#pragma unroll
                for (int v = 0; v < VEC; v++)
                    acc[r][v] = fmaf(xk, wv[v], acc[r][v]);
            }
        }
    }

    float bv[VEC];
#pragma unroll
    for (int v = 0; v < VEC; v++) bv[v] = b[lane * VEC + v];
#pragma unroll
    for (int r = 0; r < 4; r++) {
        int row = row0 + r;
        if (row < N) {
            float o[VEC];
#pragma unroll
            for (int v = 0; v < VEC; v++) o[v] = fmaxf(acc[r][v] + bv[v], 0.f);
            float* op = out32 + (size_t)row * FOUT + lane * VEC;
            if constexpr (VEC == 4)      *(float4*)op = make_float4(o[0], o[1], o[2], o[3]);
            else if constexpr (VEC == 2) *(float2*)op = make_float2(o[0], o[1]);
            else                         *op = o[0];
            if (out16) {
                __half* hp = out16 + (size_t)row * FOUT + lane * VEC;
                if constexpr (VEC == 4) {
                    uint2 t;
                    *reinterpret_cast<__half2*>(&t.x) = __floats2half2_rn(o[0], o[1]);
                    *reinterpret_cast<__half2*>(&t.y) = __floats2half2_rn(o[2], o[3]);
                    *(uint2*)hp = t;
                } else if constexpr (VEC == 2) {
                    *(__half2*)hp = __floats2half2_rn(o[0], o[1]);
                } else {
                    *hp = __float2half_rn(o[0]);
                }
            }
        }
    }
}

// ---------------------------------------------------------------------------
__global__ void __launch_bounds__(256) fc_k(
    const float* __restrict__ x, const float* __restrict__ W,
    const float* __restrict__ b, float* __restrict__ out, int N)
{
    __shared__ float sW[128 * 16];
    for (int i = threadIdx.x; i < 128 * 16; i += 256) sW[i] = W[i];
    __syncthreads();
    int warp = threadIdx.x >> 5, lane = threadIdx.x & 31;
    int row = blockIdx.x * 8 + warp;
    float xr[4];
    const float* xp = x + (size_t)row * 128;
#pragma unroll
    for (int i = 0; i < 4; i++) xr[i] = (row < N) ? xp[lane + 32 * i] : 0.f;
    float acc = 0.f;
#pragma unroll
    for (int k = 0; k < 128; k++) {
        float xk = __shfl_sync(0xffffffffu, xr[k >> 5], k & 31);
        acc = fmaf(xk, sW[k * 16 + (lane & 15)], acc);
    }
    if (row < N && lane < 16) out[(size_t)row * 16 + lane] = acc + b[lane];
}

// ---------------------------------------------------------------------------
extern "C" void kernel_launch(void* const* d_in, const int* in_sizes, int n_in,
                              void* d_out, int out_size)
{
    const float* x   = (const float*)d_in[0];
    const void*  ei  = d_in[1];
    const float* W[4]  = {(const float*)d_in[2],  (const float*)d_in[6],
                          (const float*)d_in[10], (const float*)d_in[14]};
    const float* As[4] = {(const float*)d_in[3],  (const float*)d_in[7],
                          (const float*)d_in[11], (const float*)d_in[15]};
    const float* Ad[4] = {(const float*)d_in[4],  (const float*)d_in[8],
                          (const float*)d_in[12], (const float*)d_in[16]};
    const float* B[4]  = {(const float*)d_in[5],  (const float*)d_in[9],
                          (const float*)d_in[13], (const float*)d_in[17]};
    const float* fcW = (const float*)d_in[18];
    const float* fcB = (const float*)d_in[19];

    int N = in_sizes[0] / 128;
    int E = in_sizes[1] / 2;
    int M = E + N;
    int nb = (N + SCANB - 1) / SCANB;

    float  *h0, *h1, *as_, *us, *ud;
    float2 *pair;
    __half *ha, *hb;
    int *rp, *cnt, *cur, *col, *psum;
    cudaGetSymbolAddress((void**)&h0,   g_h0);
    cudaGetSymbolAddress((void**)&h1,   g_h1);
    cudaGetSymbolAddress((void**)&ha,   g_ha);
    cudaGetSymbolAddress((void**)&hb,   g_hb);
    cudaGetSymbolAddress((void**)&as_,  g_as);
    cudaGetSymbolAddress((void**)&pair, g_pair);
    cudaGetSymbolAddress((void**)&us,   g_us);
    cudaGetSymbolAddress((void**)&ud,   g_ud);
    cudaGetSymbolAddress((void**)&rp,   g_rp);
    cudaGetSymbolAddress((void**)&cnt,  g_cnt);
    cudaGetSymbolAddress((void**)&cur,  g_cur);
    cudaGetSymbolAddress((void**)&col,  g_col);
    cudaGetSymbolAddress((void**)&psum, g_psum);

    int gemm_grid = (N + 31) / 32;
    int node_grid = (N + 7) / 8;

    // --- launches 1-3: CSR prefix ---
    detect_k<<<1, 32>>>((const int*)ei);
    zero_cnt_k<<<(N + 255) / 256, 256>>>(cnt, N);
    count_k<<<(M + 255) / 256, 256>>>(ei, E, N, cnt);

    // --- launch 4 (ncu capture slot): layer-0 GEMM (independent of CSR) ---
    gat_gemm_k<128, 32, 64><<<gemm_grid, 256>>>(x, W[0], As[0], Ad[0], ha, as_, pair, N);

    // --- CSR build continues ---
    scan1_k<<<nb, SCANB>>>(cnt, psum, N);
    scan2_k<<<1, SCANB>>>(psum, nb, rp, N);
    scan3_k<<<nb, SCANB>>>(cnt, psum, rp, cur, N);
    scatter_k<<<(M + 255) / 256, 256>>>(ei, E, N, cur, col);

    // --- Layer 0 aggregate ---
    agg_k<32, true><<<node_grid, 256>>>(rp, col, as_, pair, ha, B[0], h1, hb, N);

    // --- Layer 1: 32 -> 64  (aggregate then GEMM) ---
    wa_k<32, 64><<<1, 256>>>(W[1], As[1], Ad[1], us, ud);
    score_k<32><<<node_grid, 256>>>(h1, us, ud, as_, pair, N);
    agg_k<32, false><<<node_grid, 256>>>(rp, col, as_, pair, hb, nullptr, h0, nullptr, N);
    post_gemm_k<32, 64, 32><<<gemm_grid, 256>>>(h0, W[1], B[1], h1, ha, N);

    // --- Layer 2: 64 -> 128  (aggregate then GEMM) ---
    wa_k<64, 128><<<1, 256>>>(W[2], As[2], Ad[2], us, ud);
    score_k<64><<<node_grid, 256>>>(h1, us, ud, as_, pair, N);
    agg_k<64, false><<<node_grid, 256>>>(rp, col, as_, pair, ha, nullptr, h0, nullptr, N);
    post_gemm_k<64, 128, 64><<<gemm_grid, 256>>>(h0, W[2], B[2], h1, nullptr, N);

    // --- Layer 3: 128 -> 128 (GEMM then aggregate) ---
    gat_gemm_k<128, 128, 64><<<gemm_grid, 256>>>(h1, W[3], As[3], Ad[3], ha, as_, pair, N);
    // MEASUREMENT: duplicate agg<128> into dead scratch h1 (h1 unused after this point)
    agg_k<128, true><<<node_grid, 256>>>(rp, col, as_, pair, ha, B[3], h1, nullptr, N);
    // real layer-3 aggregate
    agg_k<128, true><<<node_grid, 256>>>(rp, col, as_, pair, ha, B[3], h0, nullptr, N);

    // --- FC: 128 -> 16 ---
    fc_k<<<node_grid, 256>>>(h0, fcW, fcB, (float*)d_out, N);
}

// round 14
// speedup vs baseline: 1.2794x; 1.2794x over previous
#include <cuda_runtime.h>
#include <cuda_fp16.h>
#include <cstdint>

// ---------------------------------------------------------------------------
// GAT (4 layers) + FC on GB300.
//   - CSR by destination built once; self-loop-score softmax (no max pass).
//   - Scores for ALL layers via u = W@a on layer input (associativity).
//   - GEMMs: smem-tiled, register-blocked (no shuffles -> low MIO pressure).
//   - Aggregation: warp/node, inline weights, fp16 gathers, col prefetch.
// ---------------------------------------------------------------------------

#define MAXN 50176
#define MAXEL 1703936
#define SCANB 256
#define KC 32

__device__ float  g_h0[(size_t)MAXN * 128];
__device__ float  g_h1[(size_t)MAXN * 128];
__device__ __half g_ha[(size_t)MAXN * 128];
__device__ __half g_hb[(size_t)MAXN * 128];
__device__ float  g_as[MAXN];
__device__ float2 g_pair[MAXN];
__device__ float  g_us[128];
__device__ float  g_ud[128];
__device__ int    g_rp[MAXN + 1];
__device__ int    g_cnt[MAXN];
__device__ int    g_cur[MAXN];
__device__ int    g_col[MAXEL];
__device__ int    g_psum[MAXN / SCANB + 1];
__device__ int    g_is64;

__device__ __forceinline__ float lrelu(float e) { return e > 0.f ? e : 0.2f * e; }

// ---------------------------------------------------------------------------
__global__ void detect_k(const int* __restrict__ w) {
    int lane = threadIdx.x;
    int bad = (w[lane * 2 + 1] != 0);
    unsigned any = __ballot_sync(0xffffffffu, bad);
    if (lane == 0) g_is64 = (any == 0u);
}

__device__ __forceinline__ int load_idx(const void* ei, size_t pos) {
    if (g_is64) return (int)((const long long*)ei)[pos];
    return ((const int*)ei)[pos];
}

// ---------------------------------------------------------------------------
__global__ void zero_cnt_k(int* cnt, int n) {
    int i = blockIdx.x * blockDim.x + threadIdx.x;
    if (i < n) cnt[i] = 0;
}

__global__ void count_k(const void* __restrict__ ei, int E, int N, int* cnt) {
    int i = blockIdx.x * blockDim.x + threadIdx.x;
    int M = E + N;
    if (i >= M) return;
    int d = (i < E) ? load_idx(ei, (size_t)E + i) : (i - E);
    if (d < 0 || d >= N) d = 0;
    atomicAdd(&cnt[d], 1);
}

__global__ void scan1_k(const int* __restrict__ cnt, int* psum, int n) {
    __shared__ int ss[8];
    int i = blockIdx.x * SCANB + threadIdx.x;
    int v = (i < n) ? cnt[i] : 0;
#pragma unroll
    for (int off = 16; off; off >>= 1) v += __shfl_xor_sync(0xffffffffu, v, off);
    if ((threadIdx.x & 31) == 0) ss[threadIdx.x >> 5] = v;
    __syncthreads();
    if (threadIdx.x == 0) {
        int t = 0;
#pragma unroll
        for (int k = 0; k < 8; k++) t += ss[k];
        psum[blockIdx.x] = t;
    }
}

__global__ void scan2_k(int* psum, int nb, int* rp, int n) {
    __shared__ int ss[SCANB];
    int tid = threadIdx.x;
    int v = (tid < nb) ? psum[tid] : 0;
    ss[tid] = v;
    __syncthreads();
#pragma unroll
    for (int off = 1; off < SCANB; off <<= 1) {
        int t = (tid >= off) ? ss[tid - off] : 0;
        __syncthreads();
        ss[tid] += t;
        __syncthreads();
    }
    if (tid < nb) psum[tid] = ss[tid] - v;
    if (tid == SCANB - 1) rp[n] = ss[SCANB - 1];
}

__global__ void scan3_k(const int* __restrict__ cnt, const int* __restrict__ psum,
                        int* rp, int* cur, int n) {
    __shared__ int ss[SCANB];
    int tid = threadIdx.x;
    int i = blockIdx.x * SCANB + tid;
    int v = (i < n) ? cnt[i] : 0;
    ss[tid] = v;
    __syncthreads();
#pragma unroll
    for (int off = 1; off < SCANB; off <<= 1) {
        int t = (tid >= off) ? ss[tid - off] : 0;
        __syncthreads();
        ss[tid] += t;
        __syncthreads();
    }
    if (i < n) {
        int r = ss[tid] - v + psum[blockIdx.x];
        rp[i] = r;
        cur[i] = r;
    }
}

__global__ void scatter_k(const void* __restrict__ ei, int E, int N,
                          int* cur, int* __restrict__ col) {
    int i = blockIdx.x * blockDim.x + threadIdx.x;
    int M = E + N;
    if (i >= M) return;
    int d, s;
    if (i < E) {
        d = load_idx(ei, (size_t)E + i);
        s = load_idx(ei, (size_t)i);
    } else {
        d = i - E;
        s = d;
    }
    if (d < 0 || d >= N) d = 0;
    if (s < 0 || s >= N) s = 0;
    int p = atomicAdd(&cur[d], 1);
    if (p >= 0 && p < MAXEL) col[p] = s;
}

// ---------------------------------------------------------------------------
// u = W @ a  (tiny). One block.
// ---------------------------------------------------------------------------
template <int FIN, int FOUT>
__global__ void wa_k(const float* __restrict__ W, const float* __restrict__ a_s,
                     const float* __restrict__ a_d,
                     float* __restrict__ us, float* __restrict__ ud) {
    int i = threadIdx.x;
    if (i >= FIN) return;
    float s1 = 0.f, s2 = 0.f;
#pragma unroll 4
    for (int j = 0; j < FOUT; j++) {
        float w = W[i * FOUT + j];
        s1 = fmaf(w, a_s[j], s1);
        s2 = fmaf(w, a_d[j], s2);
    }
    us[i] = s1;
    ud[i] = s2;
}

// ---------------------------------------------------------------------------
// Scores + pair from layer INPUT: as = x@us ; ad = x@ud ; pair=(ad,lrelu(as+ad))
// ---------------------------------------------------------------------------
template <int F>
__global__ void __launch_bounds__(256) score_k(
    const float* __restrict__ x, const float* __restrict__ us,
    const float* __restrict__ ud, float* __restrict__ as_out,
    float2* __restrict__ pair_out, int N)
{
    int node = blockIdx.x * 8 + (threadIdx.x >> 5);
    if (node >= N) return;
    int lane = threadIdx.x & 31;
    const float* xp = x + (size_t)node * F;
    float s1 = 0.f, s2 = 0.f;
#pragma unroll
    for (int i = lane; i < F; i += 32) {
        float xv = xp[i];
        s1 = fmaf(xv, us[i], s1);
        s2 = fmaf(xv, ud[i], s2);
    }
#pragma unroll
    for (int off = 16; off; off >>= 1) {
        s1 += __shfl_xor_sync(0xffffffffu, s1, off);
        s2 += __shfl_xor_sync(0xffffffffu, s2, off);
    }
    if (lane == 0) {
        as_out[node] = s1;
        pair_out[node] = make_float2(s2, lrelu(s1 + s2));
    }
}

// ---------------------------------------------------------------------------
// Tiled GEMM: out = x @ W (+bias, +relu optional). No shuffles.
// Block 256 threads, output tile RT x FOUT, thread tile TM x 4.
// Optional fp32 and fp16 outputs (nullable).
// ---------------------------------------------------------------------------
template <int FIN, int FOUT, int RT, bool DO_BIAS, bool DO_RELU>
__global__ void __launch_bounds__(256) gemm_k(
    const float* __restrict__ x, const float* __restrict__ W,
    const float* __restrict__ bias,
    float* __restrict__ out32, __half* __restrict__ out16, int N)
{
    constexpr int CT  = FOUT / 4;        // col-threads
    constexpr int RTh = 256 / CT;        // row-threads
    constexpr int TM  = RT / RTh;        // rows per thread
    constexpr int KCP = KC + 1;          // padded smem stride
    constexpr int NCH = FIN / KC;

    __shared__ float sX[RT * KCP];
    __shared__ float sW[KC * FOUT];

    const int tid = threadIdx.x;
    const int tc  = tid % CT;
    const int tr  = tid / CT;
    const int blockRow = blockIdx.x * RT;

    float acc[TM][4];
#pragma unroll
    for (int m = 0; m < TM; m++)
#pragma unroll
        for (int v = 0; v < 4; v++) acc[m][v] = 0.f;

    for (int c = 0; c < NCH; c++) {
        __syncthreads();
        // load X tile (RT x KC), float4 global loads, scalar padded stores
#pragma unroll
        for (int i = tid; i < RT * KC / 4; i += 256) {
            int r  = i / (KC / 4);
            int k4 = (i % (KC / 4)) * 4;
            int row = blockRow + r;
            float4 v = make_float4(0.f, 0.f, 0.f, 0.f);
            if (row < N)
                v = *(const float4*)(x + (size_t)row * FIN + c * KC + k4);
            float* sp = sX + r * KCP + k4;
            sp[0] = v.x; sp[1] = v.y; sp[2] = v.z; sp[3] = v.w;
        }
        // load W chunk (KC x FOUT)
#pragma unroll
        for (int i = tid; i < KC * FOUT / 4; i += 256) {
            int k  = i / (FOUT / 4);
            int f4 = (i % (FOUT / 4)) * 4;
            *(float4*)(sW + k * FOUT + f4) =
                *(const float4*)(W + (size_t)(c * KC + k) * FOUT + f4);
        }
        __syncthreads();

#pragma unroll 8
        for (int kk = 0; kk < KC; kk++) {
            float4 b = *(const float4*)(sW + kk * FOUT + tc * 4);
            float a[TM];
#pragma unroll
            for (int m = 0; m < TM; m++)
                a[m] = sX[(tr * TM + m) * KCP + kk];
#pragma unroll
            for (int m = 0; m < TM; m++) {
                acc[m][0] = fmaf(a[m], b.x, acc[m][0]);
                acc[m][1] = fmaf(a[m], b.y, acc[m][1]);
                acc[m][2] = fmaf(a[m], b.z, acc[m][2]);
                acc[m][3] = fmaf(a[m], b.w, acc[m][3]);
            }
        }
    }

    float bv[4] = {0.f, 0.f, 0.f, 0.f};
    if constexpr (DO_BIAS) {
        bv[0] = bias[tc * 4 + 0]; bv[1] = bias[tc * 4 + 1];
        bv[2] = bias[tc * 4 + 2]; bv[3] = bias[tc * 4 + 3];
    }

#pragma unroll
    for (int m = 0; m < TM; m++) {
        int row = blockRow + tr * TM + m;
        if (row >= N) continue;
        float o[4];
#pragma unroll
        for (int v = 0; v < 4; v++) {
            float t = acc[m][v] + bv[v];
            o[v] = DO_RELU ? fmaxf(t, 0.f) : t;
        }
        if (out32)
            *(float4*)(out32 + (size_t)row * FOUT + tc * 4) =
                make_float4(o[0], o[1], o[2], o[3]);
        if (out16) {
            uint2 t;
            *reinterpret_cast<__half2*>(&t.x) = __floats2half2_rn(o[0], o[1]);
            *reinterpret_cast<__half2*>(&t.y) = __floats2half2_rn(o[2], o[3]);
            *(uint2*)(out16 + (size_t)row * FOUT + tc * 4) = t;
        }
    }
}

// ---------------------------------------------------------------------------
template <int F>
__device__ __forceinline__ void gfma(const __half* __restrict__ hh, int src,
                                     int lane, float wt, float* acc) {
    constexpr int VEC = F / 32;
    const __half* p = hh + (size_t)src * F + lane * VEC;
    if constexpr (VEC == 4) {
        uint2 t = *(const uint2*)p;
        __half2 a = *reinterpret_cast<__half2*>(&t.x);
        __half2 b = *reinterpret_cast<__half2*>(&t.y);
        float2 fa = __half22float2(a), fb = __half22float2(b);
        acc[0] = fmaf(wt, fa.x, acc[0]); acc[1] = fmaf(wt, fa.y, acc[1]);
        acc[2] = fmaf(wt, fb.x, acc[2]); acc[3] = fmaf(wt, fb.y, acc[3]);
    } else if constexpr (VEC == 2) {
        float2 f = __half22float2(*(const __half2*)p);
        acc[0] = fmaf(wt, f.x, acc[0]); acc[1] = fmaf(wt, f.y, acc[1]);
    } else {
        acc[0] = fmaf(wt, __half2float(*p), acc[0]);
    }
}

// ---------------------------------------------------------------------------
// Aggregation: warp per dst node; inline weights; col prefetch pipeline.
// ---------------------------------------------------------------------------
template <int F, bool FINISH>
__global__ void __launch_bounds__(256) agg_k(
    const int* __restrict__ rp, const int* __restrict__ col,
    const float* __restrict__ as, const float2* __restrict__ pair,
    const __half* __restrict__ hh, const float* __restrict__ bias,
    float* __restrict__ out32, __half* __restrict__ out16, int N)
{
    constexpr int VEC = F / 32;
    int node = blockIdx.x * 8 + (threadIdx.x >> 5);
    if (node >= N) return;
    int lane = threadIdx.x & 31;
    int beg = rp[node], end = rp[node + 1];
    float2 pm = pair[node];
    float add = pm.x, m = pm.y;

    float acc[VEC];
#pragma unroll
    for (int v = 0; v < VEC; v++) acc[v] = 0.f;
    float s = 0.f;

    int j = beg;
    int jal = min(end, (beg + 3) & ~3);
    for (; j < jal; ++j) {
        int src = col[j];
        float wt = __expf(lrelu(as[src] + add) - m);
        s += wt;
        gfma<F>(hh, src, lane, wt, acc);
    }

    bool have = (j + 4 <= end);
    int4 c_next;
    if (have) c_next = *(const int4*)(col + j);
    while (have) {
        int4 c4 = c_next;
        j += 4;
        have = (j + 4 <= end);
        if (have) c_next = *(const int4*)(col + j);
        float a0 = as[c4.x], a1 = as[c4.y], a2 = as[c4.z], a3 = as[c4.w];
        float w0 = __expf(lrelu(a0 + add) - m);
        float w1 = __expf(lrelu(a1 + add) - m);
        float w2 = __expf(lrelu(a2 + add) - m);
        float w3 = __expf(lrelu(a3 + add) - m);
        s += (w0 + w1) + (w2 + w3);
        gfma<F>(hh, c4.x, lane, w0, acc);
        gfma<F>(hh, c4.y, lane, w1, acc);
        gfma<F>(hh, c4.z, lane, w2, acc);
        gfma<F>(hh, c4.w, lane, w3, acc);
    }
    for (; j < end; ++j) {
        int src = col[j];
        float wt = __expf(lrelu(as[src] + add) - m);
        s += wt;
        gfma<F>(hh, src, lane, wt, acc);
    }

    float inv = 1.f / s;
    float o[VEC];
#pragma unroll
    for (int v = 0; v < VEC; v++) {
        if constexpr (FINISH)
            o[v] = fmaxf(acc[v] * inv + bias[lane * VEC + v], 0.f);
        else
            o[v] = acc[v] * inv;
    }
    float* op = out32 + (size_t)node * F + lane * VEC;
    if constexpr (VEC == 4)      *(float4*)op = make_float4(o[0], o[1], o[2], o[3]);
    else if constexpr (VEC == 2) *(float2*)op = make_float2(o[0], o[1]);
    else                         *op = o[0];

    if (out16) {
        __half* hp = out16 + (size_t)node * F + lane * VEC;
        if constexpr (VEC == 4) {
            uint2 t;
            *reinterpret_cast<__half2*>(&t.x) = __floats2half2_rn(o[0], o[1]);
            *reinterpret_cast<__half2*>(&t.y) = __floats2half2_rn(o[2], o[3]);
            *(uint2*)hp = t;
        } else if constexpr (VEC == 2) {
            *(__half2*)hp = __floats2half2_rn(o[0], o[1]);
        } else {
            *hp = __float2half_rn(o[0]);
        }
    }
}

// ---------------------------------------------------------------------------
extern "C" void kernel_launch(void* const* d_in, const int* in_sizes, int n_in,
                              void* d_out, int out_size)
{
    const float* x   = (const float*)d_in[0];
    const void*  ei  = d_in[1];
    const float* W[4]  = {(const float*)d_in[2],  (const float*)d_in[6],
                          (const float*)d_in[10], (const float*)d_in[14]};
    const float* As[4] = {(const float*)d_in[3],  (const float*)d_in[7],
                          (const float*)d_in[11], (const float*)d_in[15]};
    const float* Ad[4] = {(const float*)d_in[4],  (const float*)d_in[8],
                          (const float*)d_in[12], (const float*)d_in[16]};
    const float* B[4]  = {(const float*)d_in[5],  (const float*)d_in[9],
                          (const float*)d_in[13], (const float*)d_in[17]};
    const float* fcW = (const float*)d_in[18];
    const float* fcB = (const float*)d_in[19];

    int N = in_sizes[0] / 128;
    int E = in_sizes[1] / 2;
    int M = E + N;
    int nb = (N + SCANB - 1) / SCANB;

    float  *h0, *h1, *as_, *us, *ud;
    float2 *pair;
    __half *ha, *hb;
    int *rp, *cnt, *cur, *col, *psum;
    cudaGetSymbolAddress((void**)&h0,   g_h0);
    cudaGetSymbolAddress((void**)&h1,   g_h1);
    cudaGetSymbolAddress((void**)&ha,   g_ha);
    cudaGetSymbolAddress((void**)&hb,   g_hb);
    cudaGetSymbolAddress((void**)&as_,  g_as);
    cudaGetSymbolAddress((void**)&pair, g_pair);
    cudaGetSymbolAddress((void**)&us,   g_us);
    cudaGetSymbolAddress((void**)&ud,   g_ud);
    cudaGetSymbolAddress((void**)&rp,   g_rp);
    cudaGetSymbolAddress((void**)&cnt,  g_cnt);
    cudaGetSymbolAddress((void**)&cur,  g_cur);
    cudaGetSymbolAddress((void**)&col,  g_col);
    cudaGetSymbolAddress((void**)&psum, g_psum);

    int node_grid = (N + 7) / 8;
    int g128 = (N + 127) / 128;
    int g64  = (N + 63) / 64;

    // --- launches 1-3: CSR prefix ---
    detect_k<<<1, 32>>>((const int*)ei);
    zero_cnt_k<<<(N + 255) / 256, 256>>>(cnt, N);
    count_k<<<(M + 255) / 256, 256>>>(ei, E, N, cnt);

    // --- launch 4 (ncu capture slot): new tiled layer-0 GEMM ---
    gemm_k<128, 32, 128, false, false><<<g128, 256>>>(x, W[0], nullptr, nullptr, ha, N);

    // --- CSR build continues ---
    scan1_k<<<nb, SCANB>>>(cnt, psum, N);
    scan2_k<<<1, SCANB>>>(psum, nb, rp, N);
    scan3_k<<<nb, SCANB>>>(cnt, psum, rp, cur, N);
    scatter_k<<<(M + 255) / 256, 256>>>(ei, E, N, cur, col);

    // --- Layer 0: 128 -> 32 (GEMM above; scores from input via u = W@a) ---
    wa_k<128, 32><<<1, 256>>>(W[0], As[0], Ad[0], us, ud);
    score_k<128><<<node_grid, 256>>>(x, us, ud, as_, pair, N);
    agg_k<32, true><<<node_grid, 256>>>(rp, col, as_, pair, ha, B[0], h1, hb, N);

    // --- Layer 1: 32 -> 64 (aggregate then GEMM) ---
    wa_k<32, 64><<<1, 256>>>(W[1], As[1], Ad[1], us, ud);
    score_k<32><<<node_grid, 256>>>(h1, us, ud, as_, pair, N);
    agg_k<32, false><<<node_grid, 256>>>(rp, col, as_, pair, hb, nullptr, h0, nullptr, N);
    gemm_k<32, 64, 128, true, true><<<g128, 256>>>(h0, W[1], B[1], h1, ha, N);

    // --- Layer 2: 64 -> 128 (aggregate then GEMM) ---
    wa_k<64, 128><<<1, 256>>>(W[2], As[2], Ad[2], us, ud);
    score_k<64><<<node_grid, 256>>>(h1, us, ud, as_, pair, N);
    agg_k<64, false><<<node_grid, 256>>>(rp, col, as_, pair, ha, nullptr, h0, nullptr, N);
    gemm_k<64, 128, 64, true, true><<<g64, 256>>>(h0, W[2], B[2], h1, nullptr, N);

    // --- Layer 3: 128 -> 128 (GEMM then aggregate) ---
    wa_k<128, 128><<<1, 256>>>(W[3], As[3], Ad[3], us, ud);
    score_k<128><<<node_grid, 256>>>(h1, us, ud, as_, pair, N);
    gemm_k<128, 128, 64, false, false><<<g64, 256>>>(h1, W[3], nullptr, nullptr, ha, N);
    agg_k<128, true><<<node_grid, 256>>>(rp, col, as_, pair, ha, B[3], h0, nullptr, N);

    // --- FC: 128 -> 16 (bias, no relu) ---
    gemm_k<128, 16, 128, true, false><<<g128, 256>>>(h0, fcW, fcB, (float*)d_out, nullptr, N);
}

// round 15
// speedup vs baseline: 1.2803x; 1.0007x over previous
#include <cuda_runtime.h>
#include <cuda_fp16.h>
#include <cstdint>

// ---------------------------------------------------------------------------
// GAT (4 layers) + FC on GB300.
//   - CSR build forked onto a second stream, overlapped with layer-0 GEMM
//     + scores (independent of CSR). Fork/join via events (graph-capturable).
//   - Scores for ALL layers via u = W@a on layer input (associativity).
//   - GEMMs: smem-tiled, register-blocked; RT=64 (wave-quantization friendly).
//   - Aggregation: warp/node, inline weights, fp16 gathers, col prefetch.
// ---------------------------------------------------------------------------

#define MAXN 50176
#define MAXEL 1703936
#define SCANB 256
#define KC 32

__device__ float  g_h0[(size_t)MAXN * 128];
__device__ float  g_h1[(size_t)MAXN * 128];
__device__ __half g_ha[(size_t)MAXN * 128];
__device__ __half g_hb[(size_t)MAXN * 128];
__device__ float  g_as[MAXN];
__device__ float2 g_pair[MAXN];
__device__ float  g_us[128];
__device__ float  g_ud[128];
__device__ int    g_rp[MAXN + 1];
__device__ int    g_cnt[MAXN];
__device__ int    g_cur[MAXN];
__device__ int    g_col[MAXEL];
__device__ int    g_psum[MAXN / SCANB + 1];
__device__ int    g_is64;

__device__ __forceinline__ float lrelu(float e) { return e > 0.f ? e : 0.2f * e; }

// ---------------------------------------------------------------------------
__global__ void detect_k(const int* __restrict__ w) {
    int lane = threadIdx.x;
    int bad = (w[lane * 2 + 1] != 0);
    unsigned any = __ballot_sync(0xffffffffu, bad);
    if (lane == 0) g_is64 = (any == 0u);
}

__device__ __forceinline__ int load_idx(const void* ei, size_t pos) {
    if (g_is64) return (int)((const long long*)ei)[pos];
    return ((const int*)ei)[pos];
}

// ---------------------------------------------------------------------------
__global__ void zero_cnt_k(int* cnt, int n) {
    int i = blockIdx.x * blockDim.x + threadIdx.x;
    if (i < n) cnt[i] = 0;
}

__global__ void count_k(const void* __restrict__ ei, int E, int N, int* cnt) {
    int i = blockIdx.x * blockDim.x + threadIdx.x;
    int M = E + N;
    if (i >= M) return;
    int d = (i < E) ? load_idx(ei, (size_t)E + i) : (i - E);
    if (d < 0 || d >= N) d = 0;
    atomicAdd(&cnt[d], 1);
}

__global__ void scan1_k(const int* __restrict__ cnt, int* psum, int n) {
    __shared__ int ss[8];
    int i = blockIdx.x * SCANB + threadIdx.x;
    int v = (i < n) ? cnt[i] : 0;
#pragma unroll
    for (int off = 16; off; off >>= 1) v += __shfl_xor_sync(0xffffffffu, v, off);
    if ((threadIdx.x & 31) == 0) ss[threadIdx.x >> 5] = v;
    __syncthreads();
    if (threadIdx.x == 0) {
        int t = 0;
#pragma unroll
        for (int k = 0; k < 8; k++) t += ss[k];
        psum[blockIdx.x] = t;
    }
}

__global__ void scan2_k(int* psum, int nb, int* rp, int n) {
    __shared__ int ss[SCANB];
    int tid = threadIdx.x;
    int v = (tid < nb) ? psum[tid] : 0;
    ss[tid] = v;
    __syncthreads();
#pragma unroll
    for (int off = 1; off < SCANB; off <<= 1) {
        int t = (tid >= off) ? ss[tid - off] : 0;
        __syncthreads();
        ss[tid] += t;
        __syncthreads();
    }
    if (tid < nb) psum[tid] = ss[tid] - v;
    if (tid == SCANB - 1) rp[n] = ss[SCANB - 1];
}

__global__ void scan3_k(const int* __restrict__ cnt, const int* __restrict__ psum,
                        int* rp, int* cur, int n) {
    __shared__ int ss[SCANB];
    int tid = threadIdx.x;
    int i = blockIdx.x * SCANB + tid;
    int v = (i < n) ? cnt[i] : 0;
    ss[tid] = v;
    __syncthreads();
#pragma unroll
    for (int off = 1; off < SCANB; off <<= 1) {
        int t = (tid >= off) ? ss[tid - off] : 0;
        __syncthreads();
        ss[tid] += t;
        __syncthreads();
    }
    if (i < n) {
        int r = ss[tid] - v + psum[blockIdx.x];
        rp[i] = r;
        cur[i] = r;
    }
}

__global__ void scatter_k(const void* __restrict__ ei, int E, int N,
                          int* cur, int* __restrict__ col) {
    int i = blockIdx.x * blockDim.x + threadIdx.x;
    int M = E + N;
    if (i >= M) return;
    int d, s;
    if (i < E) {
        d = load_idx(ei, (size_t)E + i);
        s = load_idx(ei, (size_t)i);
    } else {
        d = i - E;
        s = d;
    }
    if (d < 0 || d >= N) d = 0;
    if (s < 0 || s >= N) s = 0;
    int p = atomicAdd(&cur[d], 1);
    if (p >= 0 && p < MAXEL) col[p] = s;
}

// ---------------------------------------------------------------------------
template <int FIN, int FOUT>
__global__ void wa_k(const float* __restrict__ W, const float* __restrict__ a_s,
                     const float* __restrict__ a_d,
                     float* __restrict__ us, float* __restrict__ ud) {
    int i = threadIdx.x;
    if (i >= FIN) return;
    float s1 = 0.f, s2 = 0.f;
#pragma unroll 4
    for (int j = 0; j < FOUT; j++) {
        float w = W[i * FOUT + j];
        s1 = fmaf(w, a_s[j], s1);
        s2 = fmaf(w, a_d[j], s2);
    }
    us[i] = s1;
    ud[i] = s2;
}

// ---------------------------------------------------------------------------
template <int F>
__global__ void __launch_bounds__(256) score_k(
    const float* __restrict__ x, const float* __restrict__ us,
    const float* __restrict__ ud, float* __restrict__ as_out,
    float2* __restrict__ pair_out, int N)
{
    int node = blockIdx.x * 8 + (threadIdx.x >> 5);
    if (node >= N) return;
    int lane = threadIdx.x & 31;
    const float* xp = x + (size_t)node * F;
    float s1 = 0.f, s2 = 0.f;
#pragma unroll
    for (int i = lane; i < F; i += 32) {
        float xv = xp[i];
        s1 = fmaf(xv, us[i], s1);
        s2 = fmaf(xv, ud[i], s2);
    }
#pragma unroll
    for (int off = 16; off; off >>= 1) {
        s1 += __shfl_xor_sync(0xffffffffu, s1, off);
        s2 += __shfl_xor_sync(0xffffffffu, s2, off);
    }
    if (lane == 0) {
        as_out[node] = s1;
        pair_out[node] = make_float2(s2, lrelu(s1 + s2));
    }
}

// ---------------------------------------------------------------------------
// Tiled GEMM: out = x @ W (+bias, +relu optional). Block 256, tile RT x FOUT.
// ---------------------------------------------------------------------------
template <int FIN, int FOUT, int RT, bool DO_BIAS, bool DO_RELU>
__global__ void __launch_bounds__(256) gemm_k(
    const float* __restrict__ x, const float* __restrict__ W,
    const float* __restrict__ bias,
    float* __restrict__ out32, __half* __restrict__ out16, int N)
{
    constexpr int CT  = FOUT / 4;
    constexpr int RTh = 256 / CT;
    constexpr int TM  = RT / RTh;
    constexpr int KCP = KC + 1;
    constexpr int NCH = FIN / KC;

    __shared__ float sX[RT * KCP];
    __shared__ float sW[KC * FOUT];

    const int tid = threadIdx.x;
    const int tc  = tid % CT;
    const int tr  = tid / CT;
    const int blockRow = blockIdx.x * RT;

    float acc[TM][4];
#pragma unroll
    for (int m = 0; m < TM; m++)
#pragma unroll
        for (int v = 0; v < 4; v++) acc[m][v] = 0.f;

    for (int c = 0; c < NCH; c++) {
        __syncthreads();
#pragma unroll
        for (int i = tid; i < RT * KC / 4; i += 256) {
            int r  = i / (KC / 4);
            int k4 = (i % (KC / 4)) * 4;
            int row = blockRow + r;
            float4 v = make_float4(0.f, 0.f, 0.f, 0.f);
            if (row < N)
                v = *(const float4*)(x + (size_t)row * FIN + c * KC + k4);
            float* sp = sX + r * KCP + k4;
            sp[0] = v.x; sp[1] = v.y; sp[2] = v.z; sp[3] = v.w;
        }
#pragma unroll
        for (int i = tid; i < KC * FOUT / 4; i += 256) {
            int k  = i / (FOUT / 4);
            int f4 = (i % (FOUT / 4)) * 4;
            *(float4*)(sW + k * FOUT + f4) =
                *(const float4*)(W + (size_t)(c * KC + k) * FOUT + f4);
        }
        __syncthreads();

#pragma unroll 8
        for (int kk = 0; kk < KC; kk++) {
            float4 b = *(const float4*)(sW + kk * FOUT + tc * 4);
            float a[TM];
#pragma unroll
            for (int m = 0; m < TM; m++)
                a[m] = sX[(tr * TM + m) * KCP + kk];
#pragma unroll
            for (int m = 0; m < TM; m++) {
                acc[m][0] = fmaf(a[m], b.x, acc[m][0]);
                acc[m][1] = fmaf(a[m], b.y, acc[m][1]);
                acc[m][2] = fmaf(a[m], b.z, acc[m][2]);
                acc[m][3] = fmaf(a[m], b.w, acc[m][3]);
            }
        }
    }

    float bv[4] = {0.f, 0.f, 0.f, 0.f};
    if constexpr (DO_BIAS) {
        bv[0] = bias[tc * 4 + 0]; bv[1] = bias[tc * 4 + 1];
        bv[2] = bias[tc * 4 + 2]; bv[3] = bias[tc * 4 + 3];
    }

#pragma unroll
    for (int m = 0; m < TM; m++) {
        int row = blockRow + tr * TM + m;
        if (row >= N) continue;
        float o[4];
#pragma unroll
        for (int v = 0; v < 4; v++) {
            float t = acc[m][v] + bv[v];
            o[v] = DO_RELU ? fmaxf(t, 0.f) : t;
        }
        if (out32)
            *(float4*)(out32 + (size_t)row * FOUT + tc * 4) =
                make_float4(o[0], o[1], o[2], o[3]);
        if (out16) {
            uint2 t;
            *reinterpret_cast<__half2*>(&t.x) = __floats2half2_rn(o[0], o[1]);
            *reinterpret_cast<__half2*>(&t.y) = __floats2half2_rn(o[2], o[3]);
            *(uint2*)(out16 + (size_t)row * FOUT + tc * 4) = t;
        }
    }
}

// ---------------------------------------------------------------------------
template <int F>
__device__ __forceinline__ void gfma(const __half* __restrict__ hh, int src,
                                     int lane, float wt, float* acc) {
    constexpr int VEC = F / 32;
    const __half* p = hh + (size_t)src * F + lane * VEC;
    if constexpr (VEC == 4) {
        uint2 t = *(const uint2*)p;
        __half2 a = *reinterpret_cast<__half2*>(&t.x);
        __half2 b = *reinterpret_cast<__half2*>(&t.y);
        float2 fa = __half22float2(a), fb = __half22float2(b);
        acc[0] = fmaf(wt, fa.x, acc[0]); acc[1] = fmaf(wt, fa.y, acc[1]);
        acc[2] = fmaf(wt, fb.x, acc[2]); acc[3] = fmaf(wt, fb.y, acc[3]);
    } else if constexpr (VEC == 2) {
        float2 f = __half22float2(*(const __half2*)p);
        acc[0] = fmaf(wt, f.x, acc[0]); acc[1] = fmaf(wt, f.y, acc[1]);
    } else {
        acc[0] = fmaf(wt, __half2float(*p), acc[0]);
    }
}

// ---------------------------------------------------------------------------
template <int F, bool FINISH>
__global__ void __launch_bounds__(256) agg_k(
    const int* __restrict__ rp, const int* __restrict__ col,
    const float* __restrict__ as, const float2* __restrict__ pair,
    const __half* __restrict__ hh, const float* __restrict__ bias,
    float* __restrict__ out32, __half* __restrict__ out16, int N)
{
    constexpr int VEC = F / 32;
    int node = blockIdx.x * 8 + (threadIdx.x >> 5);
    if (node >= N) return;
    int lane = threadIdx.x & 31;
    int beg = rp[node], end = rp[node + 1];
    float2 pm = pair[node];
    float add = pm.x, m = pm.y;

    float acc[VEC];
#pragma unroll
    for (int v = 0; v < VEC; v++) acc[v] = 0.f;
    float s = 0.f;

    int j = beg;
    int jal = min(end, (beg + 3) & ~3);
    for (; j < jal; ++j) {
        int src = col[j];
        float wt = __expf(lrelu(as[src] + add) - m);
        s += wt;
        gfma<F>(hh, src, lane, wt, acc);
    }

    bool have = (j + 4 <= end);
    int4 c_next;
    if (have) c_next = *(const int4*)(col + j);
    while (have) {
        int4 c4 = c_next;
        j += 4;
        have = (j + 4 <= end);
        if (have) c_next = *(const int4*)(col + j);
        float a0 = as[c4.x], a1 = as[c4.y], a2 = as[c4.z], a3 = as[c4.w];
        float w0 = __expf(lrelu(a0 + add) - m);
        float w1 = __expf(lrelu(a1 + add) - m);
        float w2 = __expf(lrelu(a2 + add) - m);
        float w3 = __expf(lrelu(a3 + add) - m);
        s += (w0 + w1) + (w2 + w3);
        gfma<F>(hh, c4.x, lane, w0, acc);
        gfma<F>(hh, c4.y, lane, w1, acc);
        gfma<F>(hh, c4.z, lane, w2, acc);
        gfma<F>(hh, c4.w, lane, w3, acc);
    }
    for (; j < end; ++j) {
        int src = col[j];
        float wt = __expf(lrelu(as[src] + add) - m);
        s += wt;
        gfma<F>(hh, src, lane, wt, acc);
    }

    float inv = 1.f / s;
    float o[VEC];
#pragma unroll
    for (int v = 0; v < VEC; v++) {
        if constexpr (FINISH)
            o[v] = fmaxf(acc[v] * inv + bias[lane * VEC + v], 0.f);
        else
            o[v] = acc[v] * inv;
    }
    float* op = out32 + (size_t)node * F + lane * VEC;
    if constexpr (VEC == 4)      *(float4*)op = make_float4(o[0], o[1], o[2], o[3]);
    else if constexpr (VEC == 2) *(float2*)op = make_float2(o[0], o[1]);
    else                         *op = o[0];

    if (out16) {
        __half* hp = out16 + (size_t)node * F + lane * VEC;
        if constexpr (VEC == 4) {
            uint2 t;
            *reinterpret_cast<__half2*>(&t.x) = __floats2half2_rn(o[0], o[1]);
            *reinterpret_cast<__half2*>(&t.y) = __floats2half2_rn(o[2], o[3]);
            *(uint2*)hp = t;
        } else if constexpr (VEC == 2) {
            *(__half2*)hp = __floats2half2_rn(o[0], o[1]);
        } else {
            *hp = __float2half_rn(o[0]);
        }
    }
}

// ---------------------------------------------------------------------------
extern "C" void kernel_launch(void* const* d_in, const int* in_sizes, int n_in,
                              void* d_out, int out_size)
{
    const float* x   = (const float*)d_in[0];
    const void*  ei  = d_in[1];
    const float* W[4]  = {(const float*)d_in[2],  (const float*)d_in[6],
                          (const float*)d_in[10], (const float*)d_in[14]};
    const float* As[4] = {(const float*)d_in[3],  (const float*)d_in[7],
                          (const float*)d_in[11], (const float*)d_in[15]};
    const float* Ad[4] = {(const float*)d_in[4],  (const float*)d_in[8],
                          (const float*)d_in[12], (const float*)d_in[16]};
    const float* B[4]  = {(const float*)d_in[5],  (const float*)d_in[9],
                          (const float*)d_in[13], (const float*)d_in[17]};
    const float* fcW = (const float*)d_in[18];
    const float* fcB = (const float*)d_in[19];

    int N = in_sizes[0] / 128;
    int E = in_sizes[1] / 2;
    int M = E + N;
    int nb = (N + SCANB - 1) / SCANB;

    float  *h0, *h1, *as_, *us, *ud;
    float2 *pair;
    __half *ha, *hb;
    int *rp, *cnt, *cur, *col, *psum;
    cudaGetSymbolAddress((void**)&h0,   g_h0);
    cudaGetSymbolAddress((void**)&h1,   g_h1);
    cudaGetSymbolAddress((void**)&ha,   g_ha);
    cudaGetSymbolAddress((void**)&hb,   g_hb);
    cudaGetSymbolAddress((void**)&as_,  g_as);
    cudaGetSymbolAddress((void**)&pair, g_pair);
    cudaGetSymbolAddress((void**)&us,   g_us);
    cudaGetSymbolAddress((void**)&ud,   g_ud);
    cudaGetSymbolAddress((void**)&rp,   g_rp);
    cudaGetSymbolAddress((void**)&cnt,  g_cnt);
    cudaGetSymbolAddress((void**)&cur,  g_cur);
    cudaGetSymbolAddress((void**)&col,  g_col);
    cudaGetSymbolAddress((void**)&psum, g_psum);

    int node_grid = (N + 7) / 8;
    int g64  = (N + 63) / 64;

    // one-time side-stream + event resources (handles only; no device memory)
    static cudaStream_t s1 = nullptr;
    static cudaEvent_t evFork = nullptr, evJoin = nullptr;
    if (s1 == nullptr) {
        cudaStreamCreateWithFlags(&s1, cudaStreamNonBlocking);
        cudaEventCreateWithFlags(&evFork, cudaEventDisableTiming);
        cudaEventCreateWithFlags(&evJoin, cudaEventDisableTiming);
    }

    // --- fork: CSR build on s1, layer-0 dense work on main stream ---
    cudaEventRecord(evFork, 0);
    cudaStreamWaitEvent(s1, evFork, 0);

    detect_k<<<1, 32, 0, s1>>>((const int*)ei);
    zero_cnt_k<<<(N + 255) / 256, 256, 0, s1>>>(cnt, N);
    count_k<<<(M + 255) / 256, 256, 0, s1>>>(ei, E, N, cnt);
    scan1_k<<<nb, SCANB, 0, s1>>>(cnt, psum, N);
    scan2_k<<<1, SCANB, 0, s1>>>(psum, nb, rp, N);
    scan3_k<<<nb, SCANB, 0, s1>>>(cnt, psum, rp, cur, N);
    scatter_k<<<(M + 255) / 256, 256, 0, s1>>>(ei, E, N, cur, col);
    cudaEventRecord(evJoin, s1);

    // main stream: layer-0 GEMM + scores (independent of CSR)
    gemm_k<128, 32, 64, false, false><<<g64, 256>>>(x, W[0], nullptr, nullptr, ha, N);
    wa_k<128, 32><<<1, 256>>>(W[0], As[0], Ad[0], us, ud);
    score_k<128><<<node_grid, 256>>>(x, us, ud, as_, pair, N);

    // --- join: aggregation needs CSR ---
    cudaStreamWaitEvent(0, evJoin, 0);

    // --- Layer 0: 128 -> 32 ---
    agg_k<32, true><<<node_grid, 256>>>(rp, col, as_, pair, ha, B[0], h1, hb, N);

    // --- Layer 1: 32 -> 64 (aggregate then GEMM) ---
    wa_k<32, 64><<<1, 256>>>(W[1], As[1], Ad[1], us, ud);
    score_k<32><<<node_grid, 256>>>(h1, us, ud, as_, pair, N);
    agg_k<32, false><<<node_grid, 256>>>(rp, col, as_, pair, hb, nullptr, h0, nullptr, N);
    gemm_k<32, 64, 64, true, true><<<g64, 256>>>(h0, W[1], B[1], h1, ha, N);

    // --- Layer 2: 64 -> 128 (aggregate then GEMM) ---
    wa_k<64, 128><<<1, 256>>>(W[2], As[2], Ad[2], us, ud);
    score_k<64><<<node_grid, 256>>>(h1, us, ud, as_, pair, N);
    agg_k<64, false><<<node_grid, 256>>>(rp, col, as_, pair, ha, nullptr, h0, nullptr, N);
    gemm_k<64, 128, 64, true, true><<<g64, 256>>>(h0, W[2], B[2], h1, nullptr, N);

    // --- Layer 3: 128 -> 128 (GEMM then aggregate) ---
    wa_k<128, 128><<<1, 256>>>(W[3], As[3], Ad[3], us, ud);
    score_k<128><<<node_grid, 256>>>(h1, us, ud, as_, pair, N);
    gemm_k<128, 128, 64, false, false><<<g64, 256>>>(h1, W[3], nullptr, nullptr, ha, N);
    agg_k<128, true><<<node_grid, 256>>>(rp, col, as_, pair, ha, B[3], h0, nullptr, N);

    // --- FC: 128 -> 16 (bias, no relu) ---
    gemm_k<128, 16, 64, true, false><<<g64, 256>>>(h0, fcW, fcB, (float*)d_out, nullptr, N);
}